// round 1
// baseline (speedup 1.0000x reference)
#include <cuda_runtime.h>
#include <math.h>

#define BB 16
#define TT_ 81
#define DD 128
#define HH 8
#define BT (BB*TT_)       // 1296
#define NOUT (HH*2*DD)    // 2048

// scratch (no allocation allowed)
__device__ float g_q[BB*HH*TT_*DD];
__device__ float g_v[BB*HH*TT_*DD];
__device__ float g_bo[BB*HH*TT_*DD];

// ---------------------------------------------------------------------------
// Kernel 1: QKV GEMM.  y[m][n] = sum_k x[m][k]*W[n][k] + bias[n]
// scatter into g_q[b][h][t][d] and g_v[b][h][t][d]*head_enabled[h]
// ---------------------------------------------------------------------------
__global__ void qkv_kernel(const float* __restrict__ x,
                           const float* __restrict__ W,
                           const float* __restrict__ bias,
                           const float* __restrict__ head_en) {
    extern __shared__ float sm[];
    const int LDA = 68;                 // padded to kill STS bank conflicts
    float* As = sm;                     // [128][LDA]  (A transposed: As[k][m])
    float* Bs = sm + 128*LDA;           // [128][LDA]  (B transposed: Bs[k][n])
    int bm = blockIdx.y * 64;
    int bn = blockIdx.x * 64;
    int tid = threadIdx.x;

    {
        int m  = tid >> 2;              // 0..63
        int k0 = (tid & 3) * 32;        // 0,32,64,96
        int gm = bm + m;
        const float4* xr = (const float4*)(x + (size_t)gm * DD);
        const float4* wr = (const float4*)(W + (size_t)(bn + m) * DD);
#pragma unroll
        for (int i = 0; i < 8; i++) {
            int k = k0 + i * 4;
            float4 av = (gm < BT) ? xr[k >> 2] : make_float4(0.f,0.f,0.f,0.f);
            As[(k+0)*LDA + m] = av.x;
            As[(k+1)*LDA + m] = av.y;
            As[(k+2)*LDA + m] = av.z;
            As[(k+3)*LDA + m] = av.w;
            float4 bv = wr[k >> 2];
            Bs[(k+0)*LDA + m] = bv.x;
            Bs[(k+1)*LDA + m] = bv.y;
            Bs[(k+2)*LDA + m] = bv.z;
            Bs[(k+3)*LDA + m] = bv.w;
        }
    }
    __syncthreads();

    int tx = tid & 15, ty = tid >> 4;
    float acc[4][4];
#pragma unroll
    for (int i = 0; i < 4; i++)
#pragma unroll
        for (int j = 0; j < 4; j++) acc[i][j] = 0.f;

#pragma unroll 8
    for (int k = 0; k < 128; k++) {
        float4 a4 = *(const float4*)&As[k*LDA + ty*4];
        float4 b4 = *(const float4*)&Bs[k*LDA + tx*4];
        float av[4] = {a4.x, a4.y, a4.z, a4.w};
        float bv[4] = {b4.x, b4.y, b4.z, b4.w};
#pragma unroll
        for (int i = 0; i < 4; i++)
#pragma unroll
            for (int j = 0; j < 4; j++) acc[i][j] += av[i] * bv[j];
    }

#pragma unroll
    for (int i = 0; i < 4; i++) {
        int m = bm + ty*4 + i;
        if (m >= BT) continue;
        int bb = m / TT_, tt = m % TT_;
#pragma unroll
        for (int j = 0; j < 4; j++) {
            int n  = bn + tx*4 + j;
            int h  = n >> 8;            // / 256
            int jd = n & 255;
            float val = acc[i][j] + bias[n];
            if (jd < DD)
                g_q[(((size_t)bb*HH + h)*TT_ + tt)*DD + jd] = val;
            else
                g_v[(((size_t)bb*HH + h)*TT_ + tt)*DD + (jd - DD)] = val * head_en[h];
        }
    }
}

// ---------------------------------------------------------------------------
// Kernel 2: per-(b,h) attention: scores = -sum|q-k|/sqrt(D), softmax over s,
// * msk, ap (b==0), AV GEMM -> g_bo[b][h][t][d]
// ---------------------------------------------------------------------------
__global__ void attn_kernel(const float* __restrict__ x,
                            const float* __restrict__ wk_w,
                            const float* __restrict__ msk,
                            float* __restrict__ ap_out) {
    extern __shared__ float sm[];
    float* Qs = sm;                     // [81][128]
    float* Ks = Qs + TT_*DD;            // [81][128]
    float* Vs = Ks + TT_*DD;            // [81][128]
    float* S  = Vs + TT_*DD;            // [81][84]   S[s][t]  (s = key idx)
    const int LDS_ = 84;

    int b = blockIdx.x >> 3;
    int h = blockIdx.x & 7;
    int tid = threadIdx.x;

    const float4* q4  = (const float4*)(g_q + (((size_t)b*HH + h)*TT_)*DD);
    const float4* v4  = (const float4*)(g_v + (((size_t)b*HH + h)*TT_)*DD);
    const float4* x4  = (const float4*)(x + (size_t)b*TT_*DD);
    const float4* wk4 = (const float4*)(wk_w + h*DD);
    for (int i = tid; i < TT_*DD/4; i += 256) {
        ((float4*)Qs)[i] = q4[i];
        ((float4*)Vs)[i] = v4[i];
        float4 xv = x4[i];
        float4 wv = wk4[i & 31];
        float4 kv;
        kv.x = xv.x*wv.x; kv.y = xv.y*wv.y; kv.z = xv.z*wv.z; kv.w = xv.w*wv.w;
        ((float4*)Ks)[i] = kv;
    }
    for (int i = tid; i < TT_*LDS_; i += 256) S[i] = 0.f;
    __syncthreads();

    const float scale = 0.08838834764831843f;   // 1/sqrt(128)

    // ---- scores: 21x21 tiles of 4(t) x 4(s) ----
    for (int tile = tid; tile < 441; tile += 256) {
        int t0 = (tile / 21) * 4;
        int s0 = (tile % 21) * 4;
        float acc[4][4];
#pragma unroll
        for (int i = 0; i < 4; i++)
#pragma unroll
            for (int j = 0; j < 4; j++) acc[i][j] = 0.f;

        for (int d = 0; d < DD; d += 4) {
            float qr[4][4], kr[4][4];
#pragma unroll
            for (int i = 0; i < 4; i++) {
                int ti = min(t0 + i, TT_ - 1);
                float4 v = *(const float4*)&Qs[ti*DD + d];
                qr[i][0]=v.x; qr[i][1]=v.y; qr[i][2]=v.z; qr[i][3]=v.w;
            }
#pragma unroll
            for (int j = 0; j < 4; j++) {
                int sj = min(s0 + j, TT_ - 1);
                float4 v = *(const float4*)&Ks[sj*DD + d];
                kr[j][0]=v.x; kr[j][1]=v.y; kr[j][2]=v.z; kr[j][3]=v.w;
            }
#pragma unroll
            for (int i = 0; i < 4; i++)
#pragma unroll
                for (int j = 0; j < 4; j++) {
#pragma unroll
                    for (int e = 0; e < 4; e++)
                        acc[i][j] += fabsf(qr[i][e] - kr[j][e]);
                }
        }
#pragma unroll
        for (int i = 0; i < 4; i++) {
            if (t0 + i >= TT_) continue;
#pragma unroll
            for (int j = 0; j < 4; j++) {
                if (s0 + j >= TT_) continue;
                S[(s0 + j)*LDS_ + (t0 + i)] = -acc[i][j] * scale;
            }
        }
    }
    __syncthreads();

    // ---- softmax over s per query t, * msk, ap for b==0 ----
    if (tid < TT_) {
        int t = tid;
        float mx = -1e30f;
        for (int s = 0; s < TT_; s++) mx = fmaxf(mx, S[s*LDS_ + t]);
        float sum = 0.f;
        for (int s = 0; s < TT_; s++) {
            float e = __expf(S[s*LDS_ + t] - mx);
            sum += e;
            S[s*LDS_ + t] = e;
        }
        float inv = 1.f / sum;
        const float* mrow = msk + ((size_t)h*TT_ + t)*TT_;
        for (int s = 0; s < TT_; s++) {
            float mval = mrow[s];
            float a = S[s*LDS_ + t] * inv * mval;
            S[s*LDS_ + t] = a;
            if (b == 0)
                ap_out[((size_t)t*TT_ + s)*HH + h] = a - 1.f + mval;
        }
    }
    __syncthreads();

    // ---- AV: bo[t][d] = sum_s S[s][t] * V[s][d] ----
    float* bo = g_bo + (((size_t)b*HH + h)*TT_)*DD;
    for (int tile = tid; tile < 672; tile += 256) {   // 21 t-tiles x 32 d-tiles
        int t0 = (tile >> 5) * 4;
        int d0 = (tile & 31) * 4;
        float acc[4][4];
#pragma unroll
        for (int i = 0; i < 4; i++)
#pragma unroll
            for (int j = 0; j < 4; j++) acc[i][j] = 0.f;
        for (int s = 0; s < TT_; s++) {
            float4 a4 = *(const float4*)&S[s*LDS_ + t0];   // pad cols are 0
            float4 vv = *(const float4*)&Vs[s*DD + d0];
            float av[4] = {a4.x, a4.y, a4.z, a4.w};
            float vr[4] = {vv.x, vv.y, vv.z, vv.w};
#pragma unroll
            for (int i = 0; i < 4; i++)
#pragma unroll
                for (int j = 0; j < 4; j++) acc[i][j] += av[i] * vr[j];
        }
#pragma unroll
        for (int i = 0; i < 4; i++) {
            int t = t0 + i;
            if (t >= TT_) continue;
            float4 o = make_float4(acc[i][0], acc[i][1], acc[i][2], acc[i][3]);
            *(float4*)&bo[(size_t)t*DD + d0] = o;
        }
    }
}

// ---------------------------------------------------------------------------
// Kernel 3: g = sum_h bo;  z = quickgelu(g+4)-4;  out = x + z@Wf^T + bf
// ---------------------------------------------------------------------------
__device__ __forceinline__ float qgelu4(float s) {
    float u = s + 4.f;
    return u / (1.f + expf(-1.702f * u)) - 4.f;
}

__global__ void fanout_kernel(const float* __restrict__ x,
                              const float* __restrict__ Wf,
                              const float* __restrict__ bf,
                              float* __restrict__ out) {
    extern __shared__ float sm[];
    const int LDW = 132;
    const int LDG = 36;
    float* Ws = sm;                 // [128][LDW]  Ws[k][n]
    float* Gs = Ws + 128*LDW;       // [128][LDG]  Gs[k][m]
    int bm = blockIdx.x * 32;
    int tid = threadIdx.x;

    for (int idx = tid; idx < 128*32; idx += 256) {
        int n = idx >> 5;
        int k = (idx & 31) * 4;
        float4 wv = *(const float4*)&Wf[(size_t)n*DD + k];
        Ws[(k+0)*LDW + n] = wv.x;
        Ws[(k+1)*LDW + n] = wv.y;
        Ws[(k+2)*LDW + n] = wv.z;
        Ws[(k+3)*LDW + n] = wv.w;
    }
    for (int idx = tid; idx < 32*32; idx += 256) {
        int ml = idx >> 5;
        int k  = (idx & 31) * 4;
        int m  = bm + ml;
        float4 g = make_float4(0.f,0.f,0.f,0.f);
        if (m < BT) {
            int bb = m / TT_, t = m % TT_;
            const float* base = g_bo + (((size_t)bb*HH)*TT_ + t)*DD + k;
            float s0=0.f, s1=0.f, s2=0.f, s3=0.f;
#pragma unroll
            for (int hh = 0; hh < HH; hh++) {
                float4 v = *(const float4*)(base + (size_t)hh*TT_*DD);
                s0 += v.x; s1 += v.y; s2 += v.z; s3 += v.w;
            }
            g.x = qgelu4(s0); g.y = qgelu4(s1); g.z = qgelu4(s2); g.w = qgelu4(s3);
        }
        Gs[(k+0)*LDG + ml] = g.x;
        Gs[(k+1)*LDG + ml] = g.y;
        Gs[(k+2)*LDG + ml] = g.z;
        Gs[(k+3)*LDG + ml] = g.w;
    }
    __syncthreads();

    int tx = tid & 31;          // n tile
    int my = tid >> 5;          // m tile (0..7)
    float acc[4][4];
#pragma unroll
    for (int i = 0; i < 4; i++)
#pragma unroll
        for (int j = 0; j < 4; j++) acc[i][j] = 0.f;

#pragma unroll 8
    for (int k = 0; k < 128; k++) {
        float4 g4 = *(const float4*)&Gs[k*LDG + my*4];
        float4 w4 = *(const float4*)&Ws[k*LDW + tx*4];
        float gv[4] = {g4.x, g4.y, g4.z, g4.w};
        float wv[4] = {w4.x, w4.y, w4.z, w4.w};
#pragma unroll
        for (int i = 0; i < 4; i++)
#pragma unroll
            for (int j = 0; j < 4; j++) acc[i][j] += gv[i] * wv[j];
    }

#pragma unroll
    for (int i = 0; i < 4; i++) {
        int m = bm + my*4 + i;
        if (m >= BT) continue;
        int n0 = tx*4;
        float4 xv = *(const float4*)&x[(size_t)m*DD + n0];
        float4 bv = *(const float4*)&bf[n0];
        float4 o;
        o.x = xv.x + acc[i][0] + bv.x;
        o.y = xv.y + acc[i][1] + bv.y;
        o.z = xv.z + acc[i][2] + bv.z;
        o.w = xv.w + acc[i][3] + bv.w;
        *(float4*)&out[(size_t)m*DD + n0] = o;
    }
}

// ---------------------------------------------------------------------------
extern "C" void kernel_launch(void* const* d_in, const int* in_sizes, int n_in,
                              void* d_out, int out_size) {
    const float* x        = (const float*)d_in[0];
    const float* msk      = (const float*)d_in[1];
    const float* wqkv_w   = (const float*)d_in[2];
    const float* wqkv_b   = (const float*)d_in[3];
    const float* wk_w     = (const float*)d_in[4];
    const float* fanout_w = (const float*)d_in[5];
    const float* fanout_b = (const float*)d_in[6];
    const float* head_en  = (const float*)d_in[7];

    float* out = (float*)d_out;
    float* ap_out = out + (size_t)BT * DD;   // 165888 onward

    const int smem1 = 2 * 128 * 68 * 4;                         // 69632
    const int smem2 = (3 * TT_ * DD + TT_ * 84) * 4;            // 151632
    const int smem3 = (128 * 132 + 128 * 36) * 4;               // 86016

    cudaFuncSetAttribute(qkv_kernel,    cudaFuncAttributeMaxDynamicSharedMemorySize, smem1);
    cudaFuncSetAttribute(attn_kernel,   cudaFuncAttributeMaxDynamicSharedMemorySize, smem2);
    cudaFuncSetAttribute(fanout_kernel, cudaFuncAttributeMaxDynamicSharedMemorySize, smem3);

    dim3 grid1(NOUT / 64, (BT + 63) / 64);     // 32 x 21
    qkv_kernel<<<grid1, 256, smem1>>>(x, wqkv_w, wqkv_b, head_en);

    attn_kernel<<<BB * HH, 256, smem2>>>(x, wk_w, msk, ap_out);

    fanout_kernel<<<(BT + 31) / 32, 256, smem3>>>(x, fanout_w, fanout_b, out);
}

// round 2
// speedup vs baseline: 1.0199x; 1.0199x over previous
#include <cuda_runtime.h>
#include <math.h>

#define BB 16
#define TT_ 81
#define DD 128
#define HH 8
#define BT (BB*TT_)       // 1296
#define NOUT (HH*2*DD)    // 2048

// scratch (no allocation allowed)
__device__ float g_q[BB*HH*TT_*DD];
__device__ float g_v[BB*HH*TT_*DD];
__device__ float g_bo[BB*HH*TT_*DD];

// ---------------- packed fp32x2 helpers (sm_100+) ----------------
static __device__ __forceinline__ unsigned long long add2(unsigned long long a,
                                                          unsigned long long b) {
    unsigned long long r;
    asm("add.rn.f32x2 %0, %1, %2;" : "=l"(r) : "l"(a), "l"(b));
    return r;
}
static __device__ __forceinline__ unsigned long long fma2(unsigned long long a,
                                                          unsigned long long b,
                                                          unsigned long long c) {
    unsigned long long r;
    asm("fma.rn.f32x2 %0, %1, %2, %3;" : "=l"(r) : "l"(a), "l"(b), "l"(c));
    return r;
}
static __device__ __forceinline__ unsigned long long pack2(float x) {
    unsigned long long r;
    asm("mov.b64 %0, {%1, %1};" : "=l"(r) : "f"(x));
    return r;
}
static __device__ __forceinline__ float2 unpack2(unsigned long long v) {
    float2 f;
    asm("mov.b64 {%0, %1}, %2;" : "=f"(f.x), "=f"(f.y) : "l"(v));
    return f;
}
#define ABS2MASK 0x7FFFFFFF7FFFFFFFULL

// ---------------------------------------------------------------------------
// Kernel 1: QKV GEMM.  y[m][n] = sum_k x[m][k]*W[n][k] + bias[n]
// Block tile 64(M) x 128(N), 256 threads, 4x8 per thread, K staged 16-deep,
// double-buffered smem. Each block's N-range lies entirely in q or v of one
// head (BN=128, regions are 128 wide): scatter is 2 STG.128 per sub-row.
// ---------------------------------------------------------------------------
__global__ void __launch_bounds__(256) qkv_kernel(const float* __restrict__ x,
                                                  const float* __restrict__ W,
                                                  const float* __restrict__ bias,
                                                  const float* __restrict__ head_en) {
    __shared__ float As[2][16][64];
    __shared__ float Bs[2][16][128];

    const int bm = blockIdx.y * 64;
    const int bn = blockIdx.x * 128;
    const int tid = threadIdx.x;
    const int tx = tid & 15;          // n microtile
    const int ty = tid >> 4;          // m microtile

    // load mapping
    const int am  = tid & 63;
    const int aq  = tid >> 6;         // 0..3 : which float4 column of the 16-k chunk
    const int bnl = tid & 127;
    const int bq0 = (tid >> 7) * 2;   // 0 or 2

    const int gm = bm + am;
    const bool mok = gm < BT;
    const float4* xrow = (const float4*)(x + (size_t)(mok ? gm : 0) * DD);
    const float4* wrow = (const float4*)(W + (size_t)(bn + bnl) * DD);

    float4 av, bv0, bv1;
    const float4 z4 = make_float4(0.f, 0.f, 0.f, 0.f);

    // prologue: stage 0
    av  = mok ? xrow[aq] : z4;
    bv0 = wrow[bq0];
    bv1 = wrow[bq0 + 1];
    As[0][aq*4+0][am] = av.x;  As[0][aq*4+1][am] = av.y;
    As[0][aq*4+2][am] = av.z;  As[0][aq*4+3][am] = av.w;
    Bs[0][bq0*4+0][bnl] = bv0.x;  Bs[0][bq0*4+1][bnl] = bv0.y;
    Bs[0][bq0*4+2][bnl] = bv0.z;  Bs[0][bq0*4+3][bnl] = bv0.w;
    Bs[0][bq0*4+4][bnl] = bv1.x;  Bs[0][bq0*4+5][bnl] = bv1.y;
    Bs[0][bq0*4+6][bnl] = bv1.z;  Bs[0][bq0*4+7][bnl] = bv1.w;
    __syncthreads();

    float acc[4][8];
#pragma unroll
    for (int i = 0; i < 4; i++)
#pragma unroll
        for (int j = 0; j < 8; j++) acc[i][j] = 0.f;

    int buf = 0;
#pragma unroll 1
    for (int s = 0; s < 8; s++) {
        if (s < 7) {
            int c4 = (s + 1) * 4;
            av  = mok ? xrow[c4 + aq] : z4;
            bv0 = wrow[c4 + bq0];
            bv1 = wrow[c4 + bq0 + 1];
        }
#pragma unroll
        for (int kk = 0; kk < 16; kk++) {
            float a[4], b[8];
            *(float4*)&a[0] = *(const float4*)&As[buf][kk][ty * 4];
            *(float4*)&b[0] = *(const float4*)&Bs[buf][kk][tx * 8];
            *(float4*)&b[4] = *(const float4*)&Bs[buf][kk][tx * 8 + 4];
#pragma unroll
            for (int i = 0; i < 4; i++)
#pragma unroll
                for (int j = 0; j < 8; j++) acc[i][j] += a[i] * b[j];
        }
        if (s < 7) {
            int nb = buf ^ 1;
            As[nb][aq*4+0][am] = av.x;  As[nb][aq*4+1][am] = av.y;
            As[nb][aq*4+2][am] = av.z;  As[nb][aq*4+3][am] = av.w;
            Bs[nb][bq0*4+0][bnl] = bv0.x;  Bs[nb][bq0*4+1][bnl] = bv0.y;
            Bs[nb][bq0*4+2][bnl] = bv0.z;  Bs[nb][bq0*4+3][bnl] = bv0.w;
            Bs[nb][bq0*4+4][bnl] = bv1.x;  Bs[nb][bq0*4+5][bnl] = bv1.y;
            Bs[nb][bq0*4+6][bnl] = bv1.z;  Bs[nb][bq0*4+7][bnl] = bv1.w;
        }
        __syncthreads();
        buf ^= 1;
    }

    // epilogue: entire n-tile is q (even blockIdx.x) or v (odd)
    const bool is_v = (blockIdx.x & 1);
    const int h = blockIdx.x >> 1;
    const float sc = is_v ? head_en[h] : 1.0f;
    float* dst = is_v ? g_v : g_q;

    float4 b0 = *(const float4*)&bias[bn + tx * 8];
    float4 b1 = *(const float4*)&bias[bn + tx * 8 + 4];

#pragma unroll
    for (int i = 0; i < 4; i++) {
        int m = bm + ty * 4 + i;
        if (m >= BT) continue;
        int bb = m / TT_;
        int tt = m - bb * TT_;
        float* o = dst + (((size_t)bb * HH + h) * TT_ + tt) * DD + tx * 8;
        float4 o0, o1;
        o0.x = (acc[i][0] + b0.x) * sc;  o0.y = (acc[i][1] + b0.y) * sc;
        o0.z = (acc[i][2] + b0.z) * sc;  o0.w = (acc[i][3] + b0.w) * sc;
        o1.x = (acc[i][4] + b1.x) * sc;  o1.y = (acc[i][5] + b1.y) * sc;
        o1.z = (acc[i][6] + b1.z) * sc;  o1.w = (acc[i][7] + b1.w) * sc;
        *(float4*)o       = o0;
        *(float4*)(o + 4) = o1;
    }
}

// ---------------------------------------------------------------------------
// Kernel 2: per-(b,h) attention, 512 threads.
// scores via packed f32x2 (K stored negated), softmax over s per t, msk,
// ap (b==0), AV GEMM with fma.f32x2 -> g_bo.
// ---------------------------------------------------------------------------
__global__ void __launch_bounds__(512, 1) attn_kernel(const float* __restrict__ x,
                                                      const float* __restrict__ wk_w,
                                                      const float* __restrict__ msk,
                                                      float* __restrict__ ap_out) {
    extern __shared__ float sm[];
    float* Qs = sm;                     // [81][128]
    float* Ks = Qs + TT_*DD;            // [81][128]   holds NEGATED k
    float* Vs = Ks + TT_*DD;            // [81][128]
    float* S  = Vs + TT_*DD;            // [81][84]    S[s][t]
    const int LDS_ = 84;

    const int b = blockIdx.x >> 3;
    const int h = blockIdx.x & 7;
    const int tid = threadIdx.x;

    const float4* q4  = (const float4*)(g_q + (((size_t)b*HH + h)*TT_)*DD);
    const float4* v4  = (const float4*)(g_v + (((size_t)b*HH + h)*TT_)*DD);
    const float4* x4  = (const float4*)(x + (size_t)b*TT_*DD);
    const float4* wk4 = (const float4*)(wk_w + h*DD);
    for (int i = tid; i < TT_*DD/4; i += 512) {
        ((float4*)Qs)[i] = q4[i];
        ((float4*)Vs)[i] = v4[i];
        float4 xv = x4[i];
        float4 wv = wk4[i & 31];
        float4 kv;
        kv.x = -(xv.x*wv.x); kv.y = -(xv.y*wv.y);
        kv.z = -(xv.z*wv.z); kv.w = -(xv.w*wv.w);
        ((float4*)Ks)[i] = kv;
    }
    for (int i = tid; i < TT_*LDS_; i += 512) S[i] = 0.f;
    __syncthreads();

    const float scale = 0.08838834764831843f;   // 1/sqrt(128)

    // ---- scores: 441 tiles of 4(t) x 4(s), packed over d-pairs ----
    if (tid < 441) {
        int t0 = (tid / 21) * 4;
        int s0 = (tid % 21) * 4;
        unsigned long long acc2[4][4];
#pragma unroll
        for (int i = 0; i < 4; i++)
#pragma unroll
            for (int j = 0; j < 4; j++) acc2[i][j] = 0ULL;

#pragma unroll 4
        for (int d = 0; d < DD; d += 4) {
            ulonglong2 q2[4], k2[4];
#pragma unroll
            for (int i = 0; i < 4; i++) {
                int ti = min(t0 + i, TT_ - 1);
                q2[i] = *(const ulonglong2*)&Qs[ti*DD + d];
            }
#pragma unroll
            for (int j = 0; j < 4; j++) {
                int sj = min(s0 + j, TT_ - 1);
                k2[j] = *(const ulonglong2*)&Ks[sj*DD + d];
            }
#pragma unroll
            for (int i = 0; i < 4; i++)
#pragma unroll
                for (int j = 0; j < 4; j++) {
                    unsigned long long u = add2(q2[i].x, k2[j].x) & ABS2MASK;
                    unsigned long long w = add2(q2[i].y, k2[j].y) & ABS2MASK;
                    acc2[i][j] = add2(acc2[i][j], u);
                    acc2[i][j] = add2(acc2[i][j], w);
                }
        }
#pragma unroll
        for (int i = 0; i < 4; i++) {
            if (t0 + i >= TT_) continue;
#pragma unroll
            for (int j = 0; j < 4; j++) {
                if (s0 + j >= TT_) continue;
                float2 f = unpack2(acc2[i][j]);
                S[(s0 + j)*LDS_ + (t0 + i)] = -(f.x + f.y) * scale;
            }
        }
    }
    __syncthreads();

    // ---- softmax over s per query t, * msk, ap for b==0 ----
    if (tid < TT_) {
        int t = tid;
        float mx = -1e30f;
        for (int s = 0; s < TT_; s++) mx = fmaxf(mx, S[s*LDS_ + t]);
        float sum = 0.f;
        for (int s = 0; s < TT_; s++) {
            float e = __expf(S[s*LDS_ + t] - mx);
            sum += e;
            S[s*LDS_ + t] = e;
        }
        float inv = 1.f / sum;
        const float* mrow = msk + ((size_t)h*TT_ + t)*TT_;
        for (int s = 0; s < TT_; s++) {
            float mval = mrow[s];
            float a = S[s*LDS_ + t] * inv * mval;
            S[s*LDS_ + t] = a;
            if (b == 0)
                ap_out[((size_t)t*TT_ + s)*HH + h] = a - 1.f + mval;
        }
    }
    __syncthreads();

    // ---- AV: bo[t][d] = sum_s S[s][t] * V[s][d]  (4t x 8d tiles, fma2) ----
    float* bo = g_bo + (((size_t)b*HH + h)*TT_)*DD;
    if (tid < 336) {                      // 21 t-tiles x 16 d-tiles
        int t0 = (tid >> 4) * 4;
        int d0 = (tid & 15) * 8;
        unsigned long long acc2[4][4];
#pragma unroll
        for (int i = 0; i < 4; i++)
#pragma unroll
            for (int j = 0; j < 4; j++) acc2[i][j] = 0ULL;

#pragma unroll 3
        for (int s = 0; s < TT_; s++) {
            float4 a4 = *(const float4*)&S[s*LDS_ + t0];   // pad cols are 0
            ulonglong2 v0 = *(const ulonglong2*)&Vs[s*DD + d0];
            ulonglong2 v1 = *(const ulonglong2*)&Vs[s*DD + d0 + 4];
            unsigned long long a0 = pack2(a4.x);
            unsigned long long a1 = pack2(a4.y);
            unsigned long long a2 = pack2(a4.z);
            unsigned long long a3 = pack2(a4.w);
            acc2[0][0] = fma2(a0, v0.x, acc2[0][0]);
            acc2[0][1] = fma2(a0, v0.y, acc2[0][1]);
            acc2[0][2] = fma2(a0, v1.x, acc2[0][2]);
            acc2[0][3] = fma2(a0, v1.y, acc2[0][3]);
            acc2[1][0] = fma2(a1, v0.x, acc2[1][0]);
            acc2[1][1] = fma2(a1, v0.y, acc2[1][1]);
            acc2[1][2] = fma2(a1, v1.x, acc2[1][2]);
            acc2[1][3] = fma2(a1, v1.y, acc2[1][3]);
            acc2[2][0] = fma2(a2, v0.x, acc2[2][0]);
            acc2[2][1] = fma2(a2, v0.y, acc2[2][1]);
            acc2[2][2] = fma2(a2, v1.x, acc2[2][2]);
            acc2[2][3] = fma2(a2, v1.y, acc2[2][3]);
            acc2[3][0] = fma2(a3, v0.x, acc2[3][0]);
            acc2[3][1] = fma2(a3, v0.y, acc2[3][1]);
            acc2[3][2] = fma2(a3, v1.x, acc2[3][2]);
            acc2[3][3] = fma2(a3, v1.y, acc2[3][3]);
        }
#pragma unroll
        for (int i = 0; i < 4; i++) {
            int t = t0 + i;
            if (t >= TT_) continue;
            float2 p0 = unpack2(acc2[i][0]);
            float2 p1 = unpack2(acc2[i][1]);
            float2 p2 = unpack2(acc2[i][2]);
            float2 p3 = unpack2(acc2[i][3]);
            float4 o0 = make_float4(p0.x, p0.y, p1.x, p1.y);
            float4 o1 = make_float4(p2.x, p2.y, p3.x, p3.y);
            *(float4*)&bo[(size_t)t*DD + d0]     = o0;
            *(float4*)&bo[(size_t)t*DD + d0 + 4] = o1;
        }
    }
}

// ---------------------------------------------------------------------------
// Kernel 3: g = sum_h bo;  z = quickgelu(g+4)-4;  out = x + z@Wf^T + bf
// 162 blocks of 8 rows each.
// ---------------------------------------------------------------------------
__device__ __forceinline__ float qgelu4(float s) {
    float u = s + 4.f;
    return u / (1.f + __expf(-1.702f * u)) - 4.f;
}

__global__ void __launch_bounds__(256) fanout_kernel(const float* __restrict__ x,
                                                     const float* __restrict__ Wf,
                                                     const float* __restrict__ bf,
                                                     float* __restrict__ out) {
    extern __shared__ float sm[];
    float* Ws = sm;                 // [128][128]  Ws[k][n]
    float* Gs = sm + 128*128;       // [128][9]    Gs[k*9 + m]  (padded stride)
    const int LDG_ = 9;
    const int bm = blockIdx.x * 8;
    const int tid = threadIdx.x;

    // load Wf -> Ws[k][n]
    for (int idx = tid; idx < 4096; idx += 256) {
        int n  = idx & 127;
        int kq = idx >> 7;          // 0..31
        float4 w = *(const float4*)&Wf[(size_t)n*DD + kq*4];
        Ws[(kq*4+0)*128 + n] = w.x;
        Ws[(kq*4+1)*128 + n] = w.y;
        Ws[(kq*4+2)*128 + n] = w.z;
        Ws[(kq*4+3)*128 + n] = w.w;
    }
    // reduce heads + gelu -> Gs
    {
        int ml = tid >> 5;          // 0..7
        int k0 = (tid & 31) * 4;
        int m  = bm + ml;
        int bb = m / TT_, t = m - bb * TT_;
        const float* base = g_bo + (((size_t)bb*HH)*TT_ + t)*DD + k0;
        float s0 = 0.f, s1 = 0.f, s2 = 0.f, s3 = 0.f;
#pragma unroll
        for (int hh = 0; hh < HH; hh++) {
            float4 v = *(const float4*)(base + (size_t)hh*TT_*DD);
            s0 += v.x; s1 += v.y; s2 += v.z; s3 += v.w;
        }
        Gs[(k0+0)*LDG_ + ml] = qgelu4(s0);
        Gs[(k0+1)*LDG_ + ml] = qgelu4(s1);
        Gs[(k0+2)*LDG_ + ml] = qgelu4(s2);
        Gs[(k0+3)*LDG_ + ml] = qgelu4(s3);
    }
    __syncthreads();

    const int m_ = tid >> 5;        // 0..7
    const int nq = tid & 31;
    const int n0 = nq * 4;
    float a0 = 0.f, a1 = 0.f, a2 = 0.f, a3 = 0.f;
#pragma unroll 8
    for (int k = 0; k < 128; k++) {
        float g = Gs[k*LDG_ + m_];
        float4 w = *(const float4*)&Ws[k*128 + n0];
        a0 += g * w.x; a1 += g * w.y; a2 += g * w.z; a3 += g * w.w;
    }
    int m = bm + m_;
    float4 xv = *(const float4*)&x[(size_t)m*DD + n0];
    float4 bv = *(const float4*)&bf[n0];
    float4 o;
    o.x = xv.x + a0 + bv.x;
    o.y = xv.y + a1 + bv.y;
    o.z = xv.z + a2 + bv.z;
    o.w = xv.w + a3 + bv.w;
    *(float4*)&out[(size_t)m*DD + n0] = o;
}

// ---------------------------------------------------------------------------
extern "C" void kernel_launch(void* const* d_in, const int* in_sizes, int n_in,
                              void* d_out, int out_size) {
    const float* x        = (const float*)d_in[0];
    const float* msk      = (const float*)d_in[1];
    const float* wqkv_w   = (const float*)d_in[2];
    const float* wqkv_b   = (const float*)d_in[3];
    const float* wk_w     = (const float*)d_in[4];
    const float* fanout_w = (const float*)d_in[5];
    const float* fanout_b = (const float*)d_in[6];
    const float* head_en  = (const float*)d_in[7];

    float* out = (float*)d_out;
    float* ap_out = out + (size_t)BT * DD;   // 165888 onward

    const int smem2 = (3 * TT_ * DD + TT_ * 84) * 4;            // 151632
    const int smem3 = (128 * 128 + 128 * 9) * 4;                // 70144

    cudaFuncSetAttribute(attn_kernel,   cudaFuncAttributeMaxDynamicSharedMemorySize, smem2);
    cudaFuncSetAttribute(fanout_kernel, cudaFuncAttributeMaxDynamicSharedMemorySize, smem3);

    dim3 grid1(NOUT / 128, (BT + 63) / 64);     // 16 x 21 = 336 blocks
    qkv_kernel<<<grid1, 256>>>(x, wqkv_w, wqkv_b, head_en);

    attn_kernel<<<BB * HH, 512, smem2>>>(x, wk_w, msk, ap_out);

    fanout_kernel<<<BT / 8, 256, smem3>>>(x, fanout_w, fanout_b, out);
}

// round 3
// speedup vs baseline: 1.3071x; 1.2815x over previous
#include <cuda_runtime.h>
#include <math.h>

#define BB 16
#define TT_ 81
#define DD 128
#define HH 8
#define BT (BB*TT_)       // 1296

// scratch (no allocation allowed)
__device__ float g_bo[BB*HH*TT_*DD];

// ---------------- packed fp32x2 helpers (sm_100+) ----------------
static __device__ __forceinline__ unsigned long long add2(unsigned long long a,
                                                          unsigned long long b) {
    unsigned long long r;
    asm("add.rn.f32x2 %0, %1, %2;" : "=l"(r) : "l"(a), "l"(b));
    return r;
}
static __device__ __forceinline__ unsigned long long fma2(unsigned long long a,
                                                          unsigned long long b,
                                                          unsigned long long c) {
    unsigned long long r;
    asm("fma.rn.f32x2 %0, %1, %2, %3;" : "=l"(r) : "l"(a), "l"(b), "l"(c));
    return r;
}
static __device__ __forceinline__ unsigned long long pack2(float x) {
    unsigned long long r;
    asm("mov.b64 %0, {%1, %1};" : "=l"(r) : "f"(x));
    return r;
}
static __device__ __forceinline__ float2 unpack2(unsigned long long v) {
    float2 f;
    asm("mov.b64 {%0, %1}, %2;" : "=f"(f.x), "=f"(f.y) : "l"(v));
    return f;
}
#define ABS2MASK 0x7FFFFFFF7FFFFFFFULL

// ---- fused-kernel smem layout (float offsets) ----
#define OFF_XS   0                        // Xs [88][128]  (rows 81..87 zero) ; Msk[81*81] overlay after GEMM
#define OFF_KS   (88*DD)                  // 11264   Ks [81][128]  (negated k)
#define OFF_QS   (OFF_KS + TT_*DD)        // 21632   Qs [81][128]
#define OFF_VS   (OFF_QS + TT_*DD)        // 32000   Vs [81][128]
#define LDS_S    84
#define OFF_S    (OFF_VS + TT_*DD)        // 42368   S  [81][84]  S[s][t]
#define OFF_WS   (OFF_S + TT_*LDS_S)      // 49172   Ws [2][8][256] (split-quad permuted)
#define SMEM_FLOATS (OFF_WS + 2*8*256)    // 53268 floats = 213072 bytes

// ---------------------------------------------------------------------------
// Fused kernel: one block per (b,h), 512 threads.
//  P0: load x->Xs, Ks=-(x*wk), zero pads/S
//  P1: QKV GEMM 81x256x128 (double-buffered W chunks, FFMA2) -> Qs, Vs
//  P2: scores -|q-k| (f32x2 + AND abs)  [idle warps prefetch msk -> smem]
//  P3: softmax over s (quad-parallel per t), *msk, ap (b==0)
//  P4: AV GEMM (fma2) -> g_bo
// ---------------------------------------------------------------------------
__global__ void __launch_bounds__(512, 1)
attn_fused(const float* __restrict__ x,
           const float* __restrict__ wqkv_w,
           const float* __restrict__ wqkv_b,
           const float* __restrict__ wk_w,
           const float* __restrict__ msk,
           const float* __restrict__ head_en,
           float* __restrict__ ap_out) {
    extern __shared__ float sm[];
    float* Xs  = sm + OFF_XS;
    float* Ks  = sm + OFF_KS;
    float* Qs  = sm + OFF_QS;
    float* Vs  = sm + OFF_VS;
    float* S   = sm + OFF_S;
    float* Ws  = sm + OFF_WS;
    float* Msk = sm + OFF_XS;     // overlay (valid after GEMM phase)

    const int b = blockIdx.x >> 3;
    const int h = blockIdx.x & 7;
    const int tid = threadIdx.x;

    // ---------------- P0: loads ----------------
    {
        const float4* x4  = (const float4*)(x + (size_t)b*TT_*DD);
        const float4* wk4 = (const float4*)(wk_w + h*DD);
        for (int i = tid; i < TT_*DD/4; i += 512) {
            float4 xv = x4[i];
            ((float4*)Xs)[i] = xv;
            float4 wv = wk4[i & 31];
            float4 kv;
            kv.x = -(xv.x*wv.x); kv.y = -(xv.y*wv.y);
            kv.z = -(xv.z*wv.z); kv.w = -(xv.w*wv.w);
            ((float4*)Ks)[i] = kv;
        }
        const float4 z4 = make_float4(0.f,0.f,0.f,0.f);
        for (int i = TT_*DD/4 + tid; i < 88*DD/4; i += 512)
            ((float4*)Xs)[i] = z4;                       // zero pad rows 81..87
        for (int i = tid; i < TT_*LDS_S/4; i += 512)
            ((float4*)S)[i] = z4;                        // zero S (pad cols stay 0)
    }

    // W staging map: thread loads one float4 of the current k-chunk.
    const float* Wg = wqkv_w + ((size_t)h * 2 * DD) * DD;   // 256 rows x 128
    const int wrow = tid >> 1;              // 0..255  (output n)
    const int wkq  = (tid & 1) * 4;         // k-local 0 or 4
    // split-quad permuted position: half=(n>>2)&1, pos=(n>>3)*4 + (n&3)
    const int wdst = (((wrow >> 2) & 1) << 7) + ((wrow >> 3) << 2) + (wrow & 3);

    {   // stage chunk 0
        float4 w = *(const float4*)(Wg + wrow*DD + wkq);
        Ws[(wkq+0)*256 + wdst] = w.x;
        Ws[(wkq+1)*256 + wdst] = w.y;
        Ws[(wkq+2)*256 + wdst] = w.z;
        Ws[(wkq+3)*256 + wdst] = w.w;
    }
    __syncthreads();

    // ---------------- P1: QKV GEMM ----------------
    const int tt = tid >> 5;                // warp id = t-tile
    const int nn = tid & 31;                // n-tile (8 n each)
    const int t0 = tt * 8;
    const bool gemm_act = (tt < 11);

    unsigned long long acc[8][4];
#pragma unroll
    for (int i = 0; i < 8; i++)
#pragma unroll
        for (int p = 0; p < 4; p++) acc[i][p] = 0ULL;

    int buf = 0;
#pragma unroll 1
    for (int c = 0; c < 16; c++) {
        float4 wnext;
        if (c < 15) wnext = *(const float4*)(Wg + wrow*DD + (c+1)*8 + wkq);
        if (gemm_act) {
            const float* Wb = Ws + buf*2048;
#pragma unroll 2
            for (int kk = 0; kk < 8; kk++) {
                const int k = c*8 + kk;
                unsigned long long a2[8];
#pragma unroll
                for (int i = 0; i < 8; i++) a2[i] = pack2(Xs[(t0+i)*DD + k]);
                ulonglong2 bA = *(const ulonglong2*)&Wb[kk*256 + nn*4];
                ulonglong2 bB = *(const ulonglong2*)&Wb[kk*256 + 128 + nn*4];
#pragma unroll
                for (int i = 0; i < 8; i++) {
                    acc[i][0] = fma2(a2[i], bA.x, acc[i][0]);
                    acc[i][1] = fma2(a2[i], bA.y, acc[i][1]);
                    acc[i][2] = fma2(a2[i], bB.x, acc[i][2]);
                    acc[i][3] = fma2(a2[i], bB.y, acc[i][3]);
                }
            }
        }
        if (c < 15) {
            float* Wb2 = Ws + (buf^1)*2048;
            Wb2[(wkq+0)*256 + wdst] = wnext.x;
            Wb2[(wkq+1)*256 + wdst] = wnext.y;
            Wb2[(wkq+2)*256 + wdst] = wnext.z;
            Wb2[(wkq+3)*256 + wdst] = wnext.w;
        }
        __syncthreads();
        buf ^= 1;
    }

    // epilogue: +bias, q -> Qs ; v -> Vs * head_en
    if (gemm_act) {
        const bool isv = (nn >= 16);
        const int d0 = (nn & 15) * 8;
        const float sc = isv ? head_en[h] : 1.0f;
        float* dst = isv ? Vs : Qs;
        float4 bia0 = *(const float4*)(wqkv_b + h*256 + nn*8);
        float4 bia1 = *(const float4*)(wqkv_b + h*256 + nn*8 + 4);
#pragma unroll
        for (int i = 0; i < 8; i++) {
            int t = t0 + i;
            if (t >= TT_) break;
            float2 p0 = unpack2(acc[i][0]);
            float2 p1 = unpack2(acc[i][1]);
            float2 p2 = unpack2(acc[i][2]);
            float2 p3 = unpack2(acc[i][3]);
            float4 o0, o1;
            o0.x = (p0.x + bia0.x)*sc;  o0.y = (p0.y + bia0.y)*sc;
            o0.z = (p1.x + bia0.z)*sc;  o0.w = (p1.y + bia0.w)*sc;
            o1.x = (p2.x + bia1.x)*sc;  o1.y = (p2.y + bia1.y)*sc;
            o1.z = (p3.x + bia1.z)*sc;  o1.w = (p3.y + bia1.w)*sc;
            *(float4*)&dst[t*DD + d0]     = o0;
            *(float4*)&dst[t*DD + d0 + 4] = o1;
        }
    }
    __syncthreads();

    // ---------------- P2: scores (+ msk prefetch by idle warps) ----------------
    const float scale = 0.08838834764831843f;   // 1/sqrt(128)
    if (tid >= 448) {
        // prefetch msk[h] -> Msk (overlays dead Xs)
        const float* mg = msk + (size_t)h * TT_ * TT_;
        for (int i = tid - 448; i < TT_*TT_; i += 64) Msk[i] = mg[i];
    } else if (tid < 441) {
        int t0s = (tid / 21) * 4;
        int s0 = (tid % 21) * 4;
        unsigned long long sacc[4][4];
#pragma unroll
        for (int i = 0; i < 4; i++)
#pragma unroll
            for (int j = 0; j < 4; j++) sacc[i][j] = 0ULL;

#pragma unroll 1
        for (int d = 0; d < DD; d += 4) {
            ulonglong2 q2[4], k2[4];
#pragma unroll
            for (int i = 0; i < 4; i++) {
                int ti = min(t0s + i, TT_ - 1);
                q2[i] = *(const ulonglong2*)&Qs[ti*DD + d];
            }
#pragma unroll
            for (int j = 0; j < 4; j++) {
                int sj = min(s0 + j, TT_ - 1);
                k2[j] = *(const ulonglong2*)&Ks[sj*DD + d];
            }
#pragma unroll
            for (int i = 0; i < 4; i++)
#pragma unroll
                for (int j = 0; j < 4; j++) {
                    unsigned long long u = add2(q2[i].x, k2[j].x) & ABS2MASK;
                    unsigned long long w = add2(q2[i].y, k2[j].y) & ABS2MASK;
                    sacc[i][j] = add2(sacc[i][j], u);
                    sacc[i][j] = add2(sacc[i][j], w);
                }
        }
#pragma unroll
        for (int i = 0; i < 4; i++) {
            if (t0s + i >= TT_) continue;
#pragma unroll
            for (int j = 0; j < 4; j++) {
                if (s0 + j >= TT_) continue;
                float2 f = unpack2(sacc[i][j]);
                S[(s0 + j)*LDS_S + (t0s + i)] = -(f.x + f.y) * scale;
            }
        }
    }
    __syncthreads();

    // ---------------- P3: softmax over s (quad-parallel per t) ----------------
    if (tid < 352) {
        const int t  = tid >> 2;
        const int l4 = tid & 3;
        const bool valid = (t < TT_);
        const int sBeg = l4 * 21;
        const int sEnd = valid ? min(sBeg + 21, TT_) : sBeg;

        float mx = -1e30f;
        for (int s = sBeg; s < sEnd; s++) mx = fmaxf(mx, S[s*LDS_S + t]);
        mx = fmaxf(mx, __shfl_xor_sync(0xFFFFFFFFu, mx, 1));
        mx = fmaxf(mx, __shfl_xor_sync(0xFFFFFFFFu, mx, 2));

        float sum = 0.f;
        for (int s = sBeg; s < sEnd; s++) {
            float e = __expf(S[s*LDS_S + t] - mx);
            sum += e;
            S[s*LDS_S + t] = e;
        }
        sum += __shfl_xor_sync(0xFFFFFFFFu, sum, 1);
        sum += __shfl_xor_sync(0xFFFFFFFFu, sum, 2);
        float inv = 1.f / sum;

        for (int s = sBeg; s < sEnd; s++) {
            float mval = Msk[t*TT_ + s];
            float a = S[s*LDS_S + t] * inv * mval;
            S[s*LDS_S + t] = a;
            if (b == 0)
                ap_out[((size_t)t*TT_ + s)*HH + h] = a - 1.f + mval;
        }
    }
    __syncthreads();

    // ---------------- P4: AV GEMM -> g_bo ----------------
    float* bo = g_bo + (((size_t)b*HH + h)*TT_)*DD;
    if (tid < 336) {                      // 21 t-tiles x 16 d-tiles
        int t0a = (tid >> 4) * 4;
        int d0 = (tid & 15) * 8;
        unsigned long long av[4][4];
#pragma unroll
        for (int i = 0; i < 4; i++)
#pragma unroll
            for (int j = 0; j < 4; j++) av[i][j] = 0ULL;

#pragma unroll 2
        for (int s = 0; s < TT_; s++) {
            float4 a4 = *(const float4*)&S[s*LDS_S + t0a];   // pad cols are 0
            ulonglong2 v0 = *(const ulonglong2*)&Vs[s*DD + d0];
            ulonglong2 v1 = *(const ulonglong2*)&Vs[s*DD + d0 + 4];
            unsigned long long a0 = pack2(a4.x);
            unsigned long long a1 = pack2(a4.y);
            unsigned long long a2v = pack2(a4.z);
            unsigned long long a3 = pack2(a4.w);
            av[0][0] = fma2(a0, v0.x, av[0][0]);
            av[0][1] = fma2(a0, v0.y, av[0][1]);
            av[0][2] = fma2(a0, v1.x, av[0][2]);
            av[0][3] = fma2(a0, v1.y, av[0][3]);
            av[1][0] = fma2(a1, v0.x, av[1][0]);
            av[1][1] = fma2(a1, v0.y, av[1][1]);
            av[1][2] = fma2(a1, v1.x, av[1][2]);
            av[1][3] = fma2(a1, v1.y, av[1][3]);
            av[2][0] = fma2(a2v, v0.x, av[2][0]);
            av[2][1] = fma2(a2v, v0.y, av[2][1]);
            av[2][2] = fma2(a2v, v1.x, av[2][2]);
            av[2][3] = fma2(a2v, v1.y, av[2][3]);
            av[3][0] = fma2(a3, v0.x, av[3][0]);
            av[3][1] = fma2(a3, v0.y, av[3][1]);
            av[3][2] = fma2(a3, v1.x, av[3][2]);
            av[3][3] = fma2(a3, v1.y, av[3][3]);
        }
#pragma unroll
        for (int i = 0; i < 4; i++) {
            int t = t0a + i;
            if (t >= TT_) continue;
            float2 p0 = unpack2(av[i][0]);
            float2 p1 = unpack2(av[i][1]);
            float2 p2 = unpack2(av[i][2]);
            float2 p3 = unpack2(av[i][3]);
            float4 o0 = make_float4(p0.x, p0.y, p1.x, p1.y);
            float4 o1 = make_float4(p2.x, p2.y, p3.x, p3.y);
            *(float4*)&bo[(size_t)t*DD + d0]     = o0;
            *(float4*)&bo[(size_t)t*DD + d0 + 4] = o1;
        }
    }
}

// ---------------------------------------------------------------------------
// Kernel 2: g = sum_h bo;  z = quickgelu(g+4)-4;  out = x + z@Wf^T + bf
// 162 blocks of 8 rows each.
// ---------------------------------------------------------------------------
__device__ __forceinline__ float qgelu4(float s) {
    float u = s + 4.f;
    return u / (1.f + __expf(-1.702f * u)) - 4.f;
}

__global__ void __launch_bounds__(256) fanout_kernel(const float* __restrict__ x,
                                                     const float* __restrict__ Wf,
                                                     const float* __restrict__ bf,
                                                     float* __restrict__ out) {
    extern __shared__ float sm[];
    float* Ws = sm;                 // [128][128]  Ws[k][n]
    float* Gs = sm + 128*128;       // [128][9]    Gs[k*9 + m]  (padded stride)
    const int LDG_ = 9;
    const int bm = blockIdx.x * 8;
    const int tid = threadIdx.x;

    for (int idx = tid; idx < 4096; idx += 256) {
        int n  = idx & 127;
        int kq = idx >> 7;          // 0..31
        float4 w = *(const float4*)&Wf[(size_t)n*DD + kq*4];
        Ws[(kq*4+0)*128 + n] = w.x;
        Ws[(kq*4+1)*128 + n] = w.y;
        Ws[(kq*4+2)*128 + n] = w.z;
        Ws[(kq*4+3)*128 + n] = w.w;
    }
    {
        int ml = tid >> 5;          // 0..7
        int k0 = (tid & 31) * 4;
        int m  = bm + ml;
        int bb = m / TT_, t = m - bb * TT_;
        const float* base = g_bo + (((size_t)bb*HH)*TT_ + t)*DD + k0;
        float s0 = 0.f, s1 = 0.f, s2 = 0.f, s3 = 0.f;
#pragma unroll
        for (int hh = 0; hh < HH; hh++) {
            float4 v = *(const float4*)(base + (size_t)hh*TT_*DD);
            s0 += v.x; s1 += v.y; s2 += v.z; s3 += v.w;
        }
        Gs[(k0+0)*LDG_ + ml] = qgelu4(s0);
        Gs[(k0+1)*LDG_ + ml] = qgelu4(s1);
        Gs[(k0+2)*LDG_ + ml] = qgelu4(s2);
        Gs[(k0+3)*LDG_ + ml] = qgelu4(s3);
    }
    __syncthreads();

    const int m_ = tid >> 5;        // 0..7
    const int n0 = (tid & 31) * 4;
    float a0 = 0.f, a1 = 0.f, a2 = 0.f, a3 = 0.f;
#pragma unroll 8
    for (int k = 0; k < 128; k++) {
        float g = Gs[k*LDG_ + m_];
        float4 w = *(const float4*)&Ws[k*128 + n0];
        a0 += g * w.x; a1 += g * w.y; a2 += g * w.z; a3 += g * w.w;
    }
    int m = bm + m_;
    float4 xv = *(const float4*)&x[(size_t)m*DD + n0];
    float4 bv = *(const float4*)&bf[n0];
    float4 o;
    o.x = xv.x + a0 + bv.x;
    o.y = xv.y + a1 + bv.y;
    o.z = xv.z + a2 + bv.z;
    o.w = xv.w + a3 + bv.w;
    *(float4*)&out[(size_t)m*DD + n0] = o;
}

// ---------------------------------------------------------------------------
extern "C" void kernel_launch(void* const* d_in, const int* in_sizes, int n_in,
                              void* d_out, int out_size) {
    const float* x        = (const float*)d_in[0];
    const float* msk      = (const float*)d_in[1];
    const float* wqkv_w   = (const float*)d_in[2];
    const float* wqkv_b   = (const float*)d_in[3];
    const float* wk_w     = (const float*)d_in[4];
    const float* fanout_w = (const float*)d_in[5];
    const float* fanout_b = (const float*)d_in[6];
    const float* head_en  = (const float*)d_in[7];

    float* out = (float*)d_out;
    float* ap_out = out + (size_t)BT * DD;   // 165888 onward

    const int smemA = SMEM_FLOATS * 4;                          // 213072
    const int smem3 = (128 * 128 + 128 * 9) * 4;                // 70144

    cudaFuncSetAttribute(attn_fused,    cudaFuncAttributeMaxDynamicSharedMemorySize, smemA);
    cudaFuncSetAttribute(fanout_kernel, cudaFuncAttributeMaxDynamicSharedMemorySize, smem3);

    attn_fused<<<BB * HH, 512, smemA>>>(x, wqkv_w, wqkv_b, wk_w, msk, head_en, ap_out);

    fanout_kernel<<<BT / 8, 256, smem3>>>(x, fanout_w, fanout_b, out);
}

// round 4
// speedup vs baseline: 1.6540x; 1.2654x over previous
#include <cuda_runtime.h>
#include <math.h>

#define BB 16
#define TT_ 81
#define DD 128
#define HH 8
#define BT (BB*TT_)       // 1296

// scratch (no allocation allowed)
__device__ float g_bo[BB*HH*TT_*DD];
__device__ float g_G[BT*DD];

// ---------------- packed fp32x2 helpers (sm_100+) ----------------
static __device__ __forceinline__ unsigned long long add2(unsigned long long a,
                                                          unsigned long long b) {
    unsigned long long r;
    asm("add.rn.f32x2 %0, %1, %2;" : "=l"(r) : "l"(a), "l"(b));
    return r;
}
static __device__ __forceinline__ unsigned long long fma2(unsigned long long a,
                                                          unsigned long long b,
                                                          unsigned long long c) {
    unsigned long long r;
    asm("fma.rn.f32x2 %0, %1, %2, %3;" : "=l"(r) : "l"(a), "l"(b), "l"(c));
    return r;
}
static __device__ __forceinline__ unsigned long long pack2(float x) {
    unsigned long long r;
    asm("mov.b64 %0, {%1, %1};" : "=l"(r) : "f"(x));
    return r;
}
static __device__ __forceinline__ float2 unpack2(unsigned long long v) {
    float2 f;
    asm("mov.b64 {%0, %1}, %2;" : "=f"(f.x), "=f"(f.y) : "l"(v));
    return f;
}
#define ABS2MASK 0x7FFFFFFF7FFFFFFFULL

// ---- fused-kernel smem layout (float offsets) ----
#define OFF_XS   0                        // Xs [88][128] (rows 81..87 zero); Msk[6561] overlay after GEMM
#define OFF_KT   (88*DD)                  // 11264  KT2: 64 d-pairs x 84 s  (float2, NEGATED k) = 10752 fl
#define OFF_QS   (OFF_KT + 64*84*2)       // 22016  Qs [81][128]
#define OFF_VS   (OFF_QS + TT_*DD)        // 32384  Vs [81][128]
#define LDS_S    84
#define OFF_S    (OFF_VS + TT_*DD)        // 42752  S  [81][84]  S[s][t]
#define OFF_WS   (OFF_S + TT_*LDS_S)      // 49556  Ws [2][8][256]
#define SMEM_FLOATS (OFF_WS + 2*8*256)    // 53652 floats = 214608 bytes

// ---------------------------------------------------------------------------
// Fused kernel: one block per (b,h), 512 threads.
// ---------------------------------------------------------------------------
__global__ void __launch_bounds__(512, 1)
attn_fused(const float* __restrict__ x,
           const float* __restrict__ wqkv_w,
           const float* __restrict__ wqkv_b,
           const float* __restrict__ wk_w,
           const float* __restrict__ msk,
           const float* __restrict__ head_en,
           float* __restrict__ ap_out) {
    extern __shared__ float sm[];
    float* Xs  = sm + OFF_XS;
    float* KT  = sm + OFF_KT;     // float index; row stride (per d-pair) = 168 floats
    float* Qs  = sm + OFF_QS;
    float* Vs  = sm + OFF_VS;
    float* S   = sm + OFF_S;
    float* Ws  = sm + OFF_WS;
    float* Msk = sm + OFF_XS;     // overlay (valid after GEMM phase)

    const int b = blockIdx.x >> 3;
    const int h = blockIdx.x & 7;
    const int tid = threadIdx.x;

    // ---------------- P0: loads ----------------
    {
        const float4* x4  = (const float4*)(x + (size_t)b*TT_*DD);
        const float4* wk4 = (const float4*)(wk_w + h*DD);
        for (int i = tid; i < TT_*DD/4; i += 512) {
            float4 xv = x4[i];
            ((float4*)Xs)[i] = xv;
            float4 wv = wk4[i & 31];
            // KT2[(d>>1)*84 + s] = (-x*wk at d, d+1) ; d = (i&31)*4
            int s  = i >> 5;
            int dp = (i & 31) * 2;            // d-pair index of d0
            float2 k0, k1;
            k0.x = -(xv.x*wv.x); k0.y = -(xv.y*wv.y);
            k1.x = -(xv.z*wv.z); k1.y = -(xv.w*wv.w);
            *(float2*)&KT[(dp    )*168 + s*2] = k0;
            *(float2*)&KT[(dp + 1)*168 + s*2] = k1;
        }
        const float4 z4 = make_float4(0.f,0.f,0.f,0.f);
        for (int i = TT_*DD/4 + tid; i < 88*DD/4; i += 512)
            ((float4*)Xs)[i] = z4;                       // zero pad rows 81..87
        for (int i = tid; i < TT_*LDS_S/4; i += 512)
            ((float4*)S)[i] = z4;                        // zero S (pad cols stay 0)
        // zero KT pad s = 81..83 for all 64 d-pairs (64*3 float2 = 192)
        for (int i = tid; i < 192; i += 512) {
            int dp = i / 3, s = 81 + (i % 3);
            *(float2*)&KT[dp*168 + s*2] = make_float2(0.f, 0.f);
        }
    }

    // W staging map
    const float* Wg = wqkv_w + ((size_t)h * 2 * DD) * DD;   // 256 rows x 128
    const int wrow = tid >> 1;              // 0..255  (output n)
    const int wkq  = (tid & 1) * 4;         // k-local 0 or 4
    const int wdst = (((wrow >> 2) & 1) << 7) + ((wrow >> 3) << 2) + (wrow & 3);

    {   // stage chunk 0
        float4 w = *(const float4*)(Wg + wrow*DD + wkq);
        Ws[(wkq+0)*256 + wdst] = w.x;
        Ws[(wkq+1)*256 + wdst] = w.y;
        Ws[(wkq+2)*256 + wdst] = w.z;
        Ws[(wkq+3)*256 + wdst] = w.w;
    }
    __syncthreads();

    // ---------------- P1: QKV GEMM ----------------
    const int tt = tid >> 5;                // warp id = t-tile
    const int nn = tid & 31;                // n-tile (8 n each)
    const int t0 = tt * 8;
    const bool gemm_act = (tt < 11);

    unsigned long long acc[8][4];
#pragma unroll
    for (int i = 0; i < 8; i++)
#pragma unroll
        for (int p = 0; p < 4; p++) acc[i][p] = 0ULL;

    int buf = 0;
#pragma unroll 1
    for (int c = 0; c < 16; c++) {
        float4 wnext;
        if (c < 15) wnext = *(const float4*)(Wg + wrow*DD + (c+1)*8 + wkq);
        if (gemm_act) {
            const float* Wb = Ws + buf*2048;
#pragma unroll 2
            for (int kk = 0; kk < 8; kk++) {
                const int k = c*8 + kk;
                unsigned long long a2[8];
#pragma unroll
                for (int i = 0; i < 8; i++) a2[i] = pack2(Xs[(t0+i)*DD + k]);
                ulonglong2 bA = *(const ulonglong2*)&Wb[kk*256 + nn*4];
                ulonglong2 bB = *(const ulonglong2*)&Wb[kk*256 + 128 + nn*4];
#pragma unroll
                for (int i = 0; i < 8; i++) {
                    acc[i][0] = fma2(a2[i], bA.x, acc[i][0]);
                    acc[i][1] = fma2(a2[i], bA.y, acc[i][1]);
                    acc[i][2] = fma2(a2[i], bB.x, acc[i][2]);
                    acc[i][3] = fma2(a2[i], bB.y, acc[i][3]);
                }
            }
        }
        if (c < 15) {
            float* Wb2 = Ws + (buf^1)*2048;
            Wb2[(wkq+0)*256 + wdst] = wnext.x;
            Wb2[(wkq+1)*256 + wdst] = wnext.y;
            Wb2[(wkq+2)*256 + wdst] = wnext.z;
            Wb2[(wkq+3)*256 + wdst] = wnext.w;
        }
        __syncthreads();
        buf ^= 1;
    }

    // epilogue: +bias, q -> Qs ; v -> Vs * head_en
    if (gemm_act) {
        const bool isv = (nn >= 16);
        const int d0 = (nn & 15) * 8;
        const float sc = isv ? head_en[h] : 1.0f;
        float* dst = isv ? Vs : Qs;
        float4 bia0 = *(const float4*)(wqkv_b + h*256 + nn*8);
        float4 bia1 = *(const float4*)(wqkv_b + h*256 + nn*8 + 4);
#pragma unroll
        for (int i = 0; i < 8; i++) {
            int t = t0 + i;
            if (t >= TT_) break;
            float2 p0 = unpack2(acc[i][0]);
            float2 p1 = unpack2(acc[i][1]);
            float2 p2 = unpack2(acc[i][2]);
            float2 p3 = unpack2(acc[i][3]);
            float4 o0, o1;
            o0.x = (p0.x + bia0.x)*sc;  o0.y = (p0.y + bia0.y)*sc;
            o0.z = (p1.x + bia0.z)*sc;  o0.w = (p1.y + bia0.w)*sc;
            o1.x = (p2.x + bia1.x)*sc;  o1.y = (p2.y + bia1.y)*sc;
            o1.z = (p3.x + bia1.z)*sc;  o1.w = (p3.y + bia1.w)*sc;
            *(float4*)&dst[t*DD + d0]     = o0;
            *(float4*)&dst[t*DD + d0 + 4] = o1;
        }
    }
    __syncthreads();

    // ---------------- P2: scores (+ msk prefetch by idle warps) ----------------
    const float scale = 0.08838834764831843f;   // 1/sqrt(128)
    if (tid >= 448) {
        const float* mg = msk + (size_t)h * TT_ * TT_;
        for (int i = tid - 448; i < TT_*TT_; i += 64) Msk[i] = mg[i];
    } else if (tid < 441) {
        const int t0s = (tid / 21) * 4;
        const int s0 = (tid % 21) * 4;
        int ti[4];
#pragma unroll
        for (int i = 0; i < 4; i++) ti[i] = min(t0s + i, TT_ - 1);

        unsigned long long sacc[4][4];
#pragma unroll
        for (int i = 0; i < 4; i++)
#pragma unroll
            for (int j = 0; j < 4; j++) sacc[i][j] = 0ULL;

#pragma unroll 1
        for (int d = 0; d < DD; d += 4) {
            const int dp = d >> 1;
            ulonglong2 q[4];
#pragma unroll
            for (int i = 0; i < 4; i++)
                q[i] = *(const ulonglong2*)&Qs[ti[i]*DD + d];
            // k pairs: (d,d+1) at s0..s0+3 and (d+2,d+3) at s0..s0+3
            ulonglong2 ka = *(const ulonglong2*)&KT[(dp  )*168 + s0*2];      // s0, s0+1
            ulonglong2 kb = *(const ulonglong2*)&KT[(dp  )*168 + s0*2 + 4];  // s0+2, s0+3
            ulonglong2 kc = *(const ulonglong2*)&KT[(dp+1)*168 + s0*2];
            ulonglong2 kd = *(const ulonglong2*)&KT[(dp+1)*168 + s0*2 + 4];
#pragma unroll
            for (int i = 0; i < 4; i++) {
                unsigned long long u;
                u = add2(q[i].x, ka.x) & ABS2MASK;  sacc[i][0] = add2(sacc[i][0], u);
                u = add2(q[i].y, kc.x) & ABS2MASK;  sacc[i][0] = add2(sacc[i][0], u);
                u = add2(q[i].x, ka.y) & ABS2MASK;  sacc[i][1] = add2(sacc[i][1], u);
                u = add2(q[i].y, kc.y) & ABS2MASK;  sacc[i][1] = add2(sacc[i][1], u);
                u = add2(q[i].x, kb.x) & ABS2MASK;  sacc[i][2] = add2(sacc[i][2], u);
                u = add2(q[i].y, kd.x) & ABS2MASK;  sacc[i][2] = add2(sacc[i][2], u);
                u = add2(q[i].x, kb.y) & ABS2MASK;  sacc[i][3] = add2(sacc[i][3], u);
                u = add2(q[i].y, kd.y) & ABS2MASK;  sacc[i][3] = add2(sacc[i][3], u);
            }
        }
#pragma unroll
        for (int i = 0; i < 4; i++) {
            if (t0s + i >= TT_) continue;
#pragma unroll
            for (int j = 0; j < 4; j++) {
                if (s0 + j >= TT_) continue;
                float2 f = unpack2(sacc[i][j]);
                S[(s0 + j)*LDS_S + (t0s + i)] = -(f.x + f.y) * scale;
            }
        }
    }
    __syncthreads();

    // ---------------- P3: softmax over s (quad-parallel per t) ----------------
    if (tid < 352) {
        const int t  = tid >> 2;
        const int l4 = tid & 3;
        const bool valid = (t < TT_);
        const int sBeg = l4 * 21;
        const int sEnd = valid ? min(sBeg + 21, TT_) : sBeg;

        float mx = -1e30f;
        for (int s = sBeg; s < sEnd; s++) mx = fmaxf(mx, S[s*LDS_S + t]);
        mx = fmaxf(mx, __shfl_xor_sync(0xFFFFFFFFu, mx, 1));
        mx = fmaxf(mx, __shfl_xor_sync(0xFFFFFFFFu, mx, 2));

        float sum = 0.f;
        for (int s = sBeg; s < sEnd; s++) {
            float e = __expf(S[s*LDS_S + t] - mx);
            sum += e;
            S[s*LDS_S + t] = e;
        }
        sum += __shfl_xor_sync(0xFFFFFFFFu, sum, 1);
        sum += __shfl_xor_sync(0xFFFFFFFFu, sum, 2);
        float inv = 1.f / sum;

        for (int s = sBeg; s < sEnd; s++) {
            float mval = Msk[t*TT_ + s];
            float a = S[s*LDS_S + t] * inv * mval;
            S[s*LDS_S + t] = a;
            if (b == 0)
                ap_out[((size_t)t*TT_ + s)*HH + h] = a - 1.f + mval;
        }
    }
    __syncthreads();

    // ---------------- P4: AV GEMM -> g_bo ----------------
    float* bo = g_bo + (((size_t)b*HH + h)*TT_)*DD;
    if (tid < 336) {                      // 21 t-tiles x 16 d-tiles
        int t0a = (tid >> 4) * 4;
        int d0 = (tid & 15) * 8;
        unsigned long long av[4][4];
#pragma unroll
        for (int i = 0; i < 4; i++)
#pragma unroll
            for (int j = 0; j < 4; j++) av[i][j] = 0ULL;

#pragma unroll 2
        for (int s = 0; s < TT_; s++) {
            float4 a4 = *(const float4*)&S[s*LDS_S + t0a];   // pad cols are 0
            ulonglong2 v0 = *(const ulonglong2*)&Vs[s*DD + d0];
            ulonglong2 v1 = *(const ulonglong2*)&Vs[s*DD + d0 + 4];
            unsigned long long a0 = pack2(a4.x);
            unsigned long long a1 = pack2(a4.y);
            unsigned long long a2v = pack2(a4.z);
            unsigned long long a3 = pack2(a4.w);
            av[0][0] = fma2(a0, v0.x, av[0][0]);
            av[0][1] = fma2(a0, v0.y, av[0][1]);
            av[0][2] = fma2(a0, v1.x, av[0][2]);
            av[0][3] = fma2(a0, v1.y, av[0][3]);
            av[1][0] = fma2(a1, v0.x, av[1][0]);
            av[1][1] = fma2(a1, v0.y, av[1][1]);
            av[1][2] = fma2(a1, v1.x, av[1][2]);
            av[1][3] = fma2(a1, v1.y, av[1][3]);
            av[2][0] = fma2(a2v, v0.x, av[2][0]);
            av[2][1] = fma2(a2v, v0.y, av[2][1]);
            av[2][2] = fma2(a2v, v1.x, av[2][2]);
            av[2][3] = fma2(a2v, v1.y, av[2][3]);
            av[3][0] = fma2(a3, v0.x, av[3][0]);
            av[3][1] = fma2(a3, v0.y, av[3][1]);
            av[3][2] = fma2(a3, v1.x, av[3][2]);
            av[3][3] = fma2(a3, v1.y, av[3][3]);
        }
#pragma unroll
        for (int i = 0; i < 4; i++) {
            int t = t0a + i;
            if (t >= TT_) continue;
            float2 p0 = unpack2(av[i][0]);
            float2 p1 = unpack2(av[i][1]);
            float2 p2 = unpack2(av[i][2]);
            float2 p3 = unpack2(av[i][3]);
            float4 o0 = make_float4(p0.x, p0.y, p1.x, p1.y);
            float4 o1 = make_float4(p2.x, p2.y, p3.x, p3.y);
            *(float4*)&bo[(size_t)t*DD + d0]     = o0;
            *(float4*)&bo[(size_t)t*DD + d0 + 4] = o1;
        }
    }
}

// ---------------------------------------------------------------------------
// Kernel 2a: G[m][d] = qgelu(sum_h bo[b][h][t][d])   (m = b*81+t)
// 41472 threads, one float4 each, MLP 8.
// ---------------------------------------------------------------------------
__device__ __forceinline__ float qgelu4(float s) {
    float u = s + 4.f;
    return u / (1.f + __expf(-1.702f * u)) - 4.f;
}

__global__ void __launch_bounds__(128) reduce_gelu_kernel() {
    int idx = blockIdx.x * 128 + threadIdx.x;   // 0..41471
    int m  = idx >> 5;
    int kq = idx & 31;
    int bb = m / TT_, t = m - bb * TT_;
    const float4* base = (const float4*)g_bo + ((size_t)(bb*HH)*TT_ + t)*32 + kq;
    float s0 = 0.f, s1 = 0.f, s2 = 0.f, s3 = 0.f;
#pragma unroll
    for (int hh = 0; hh < HH; hh++) {
        float4 v = base[(size_t)hh*TT_*32];
        s0 += v.x; s1 += v.y; s2 += v.z; s3 += v.w;
    }
    float4 g;
    g.x = qgelu4(s0); g.y = qgelu4(s1); g.z = qgelu4(s2); g.w = qgelu4(s3);
    ((float4*)g_G)[(size_t)m*32 + kq] = g;
}

// ---------------------------------------------------------------------------
// Kernel 2b: out = x + G@Wf^T + bf.  Grid 162: (mtile 0..80) x (n-half 0..1).
// Block = 16 rows x 64 cols, 256 threads, ~41.5KB smem -> 5 blocks/SM.
// ---------------------------------------------------------------------------
__global__ void __launch_bounds__(256) fanout_kernel(const float* __restrict__ x,
                                                     const float* __restrict__ Wf,
                                                     const float* __restrict__ bf,
                                                     float* __restrict__ out) {
    extern __shared__ float sm[];
    float* Ws = sm;                 // [128][64]  Ws[k][n]
    float* Gs = sm + 128*64;        // [128][17]  Gs[k*17 + m]
    const int LDG_ = 17;
    const int mtile = blockIdx.x >> 1;
    const int half  = blockIdx.x & 1;
    const int m0 = mtile * 16;
    const int nbase = half * 64;
    const int tid = threadIdx.x;

    // stage Wf half -> Ws[k][n]   (8 passes of 4 kq x 64 n; conflict-free STS)
    {
        int n  = tid & 63;
        int k4 = tid >> 6;              // 0..3
        const float* wr = Wf + (size_t)(nbase + n) * DD;
#pragma unroll
        for (int p = 0; p < 8; p++) {
            int kq = p * 4 + k4;        // 0..31
            float4 w = *(const float4*)(wr + kq * 4);
            Ws[(kq*4+0)*64 + n] = w.x;
            Ws[(kq*4+1)*64 + n] = w.y;
            Ws[(kq*4+2)*64 + n] = w.z;
            Ws[(kq*4+3)*64 + n] = w.w;
        }
    }
    // stage G rows -> Gs[k][m]  (2 float4 per thread)
    {
#pragma unroll
        for (int p = 0; p < 2; p++) {
            int i  = p * 256 + tid;     // 0..511
            int ml = i >> 5;
            int kq = i & 31;
            float4 g = ((const float4*)g_G)[(size_t)(m0 + ml)*32 + kq];
            Gs[(kq*4+0)*LDG_ + ml] = g.x;
            Gs[(kq*4+1)*LDG_ + ml] = g.y;
            Gs[(kq*4+2)*LDG_ + ml] = g.z;
            Gs[(kq*4+3)*LDG_ + ml] = g.w;
        }
    }
    __syncthreads();

    const int m_ = tid >> 4;            // 0..15
    const int n0 = (tid & 15) * 4;      // 0..60
    float a0 = 0.f, a1 = 0.f, a2 = 0.f, a3 = 0.f;
#pragma unroll 8
    for (int k = 0; k < 128; k++) {
        float g = Gs[k*LDG_ + m_];
        float4 w = *(const float4*)&Ws[k*64 + n0];
        a0 += g * w.x; a1 += g * w.y; a2 += g * w.z; a3 += g * w.w;
    }
    int m = m0 + m_;
    int ng = nbase + n0;
    float4 xv = *(const float4*)&x[(size_t)m*DD + ng];
    float4 bv = *(const float4*)&bf[ng];
    float4 o;
    o.x = xv.x + a0 + bv.x;
    o.y = xv.y + a1 + bv.y;
    o.z = xv.z + a2 + bv.z;
    o.w = xv.w + a3 + bv.w;
    *(float4*)&out[(size_t)m*DD + ng] = o;
}

// ---------------------------------------------------------------------------
extern "C" void kernel_launch(void* const* d_in, const int* in_sizes, int n_in,
                              void* d_out, int out_size) {
    const float* x        = (const float*)d_in[0];
    const float* msk      = (const float*)d_in[1];
    const float* wqkv_w   = (const float*)d_in[2];
    const float* wqkv_b   = (const float*)d_in[3];
    const float* wk_w     = (const float*)d_in[4];
    const float* fanout_w = (const float*)d_in[5];
    const float* fanout_b = (const float*)d_in[6];
    const float* head_en  = (const float*)d_in[7];

    float* out = (float*)d_out;
    float* ap_out = out + (size_t)BT * DD;   // 165888 onward

    const int smemA = SMEM_FLOATS * 4;                   // 214608
    const int smem3 = (128*64 + 128*17) * 4 + 16;        // ~41.5KB

    cudaFuncSetAttribute(attn_fused,    cudaFuncAttributeMaxDynamicSharedMemorySize, smemA);
    cudaFuncSetAttribute(fanout_kernel, cudaFuncAttributeMaxDynamicSharedMemorySize, smem3);

    attn_fused<<<BB * HH, 512, smemA>>>(x, wqkv_w, wqkv_b, wk_w, msk, head_en, ap_out);

    reduce_gelu_kernel<<<324, 128>>>();

    fanout_kernel<<<162, 256, smem3>>>(x, fanout_w, fanout_b, out);
}

// round 5
// speedup vs baseline: 1.6610x; 1.0042x over previous
#include <cuda_runtime.h>
#include <math.h>

#define BB 16
#define TT_ 81
#define DD 128
#define HH 8
#define BT (BB*TT_)       // 1296

// scratch (no allocation allowed)
__device__ float g_bo[BB*HH*TT_*DD];

// ---------------- packed fp32x2 helpers (sm_100+) ----------------
static __device__ __forceinline__ unsigned long long add2(unsigned long long a,
                                                          unsigned long long b) {
    unsigned long long r;
    asm("add.rn.f32x2 %0, %1, %2;" : "=l"(r) : "l"(a), "l"(b));
    return r;
}
static __device__ __forceinline__ unsigned long long fma2(unsigned long long a,
                                                          unsigned long long b,
                                                          unsigned long long c) {
    unsigned long long r;
    asm("fma.rn.f32x2 %0, %1, %2, %3;" : "=l"(r) : "l"(a), "l"(b), "l"(c));
    return r;
}
static __device__ __forceinline__ unsigned long long pack2(float x) {
    unsigned long long r;
    asm("mov.b64 %0, {%1, %1};" : "=l"(r) : "f"(x));
    return r;
}
static __device__ __forceinline__ float2 unpack2(unsigned long long v) {
    float2 f;
    asm("mov.b64 {%0, %1}, %2;" : "=f"(f.x), "=f"(f.y) : "l"(v));
    return f;
}
#define ABS2MASK 0x7FFFFFFF7FFFFFFFULL

// ---- fused-kernel smem layout (float offsets) ----
#define XST_LD   90
#define OFF_XST  0                        // XsT [128][90]  (t cols 81..89 zero); Msk overlay after P1
#define OFF_KT   (128*XST_LD)             // 11520  KT2: 64 d-pairs x 84 s (float2, NEGATED k)
#define OFF_QS   (OFF_KT + 64*84*2)       // 22272  Qs [81][128]
#define OFF_VS   (OFF_QS + TT_*DD)        // 32640  Vs [81][128]
#define LDS_S    84
#define OFF_S    (OFF_VS + TT_*DD)        // 43008  S  [81][84]  S[s][t]
#define OFF_WS   (OFF_S + TT_*LDS_S)      // 49812  Ws [2][8][256] (plain [k][n])
#define SMEM_FLOATS (OFF_WS + 2*8*256)    // 53908 floats = 215632 bytes

// ---------------------------------------------------------------------------
// Fused kernel: one block per (b,h), 512 threads.
//  P0: x -> XsT (transposed), Ks -> KT (negated, d-pair x s), zero pads/S
//  P1: QKV GEMM 81x256x128, FFMA2 with (t,t+1)-packed lanes -> Qs, Vs
//  P2: scores -|q-k| (f32x2 + AND abs)  [idle warps prefetch msk over XsT]
//  P3: softmax over s (quad-parallel per t), *msk, ap (b==0)
//  P4: AV GEMM (fma2) -> g_bo
// ---------------------------------------------------------------------------
__global__ void __launch_bounds__(512, 1)
attn_fused(const float* __restrict__ x,
           const float* __restrict__ wqkv_w,
           const float* __restrict__ wqkv_b,
           const float* __restrict__ wk_w,
           const float* __restrict__ msk,
           const float* __restrict__ head_en,
           float* __restrict__ ap_out) {
    extern __shared__ float sm[];
    float* XsT = sm + OFF_XST;
    float* KT  = sm + OFF_KT;     // row stride (per d-pair) = 168 floats
    float* Qs  = sm + OFF_QS;
    float* Vs  = sm + OFF_VS;
    float* S   = sm + OFF_S;
    float* Ws  = sm + OFF_WS;
    float* Msk = sm + OFF_XST;    // overlay (valid after P1)

    const int b = blockIdx.x >> 3;
    const int h = blockIdx.x & 7;
    const int tid = threadIdx.x;

    // ---------------- P0: loads ----------------
    {
        const float4* x4  = (const float4*)(x + (size_t)b*TT_*DD);
        const float4* wk4 = (const float4*)(wk_w + h*DD);
        for (int i = tid; i < TT_*DD/4; i += 512) {
            float4 xv = x4[i];
            int t  = i >> 5;
            int d0 = (i & 31) * 4;
            XsT[(d0+0)*XST_LD + t] = xv.x;
            XsT[(d0+1)*XST_LD + t] = xv.y;
            XsT[(d0+2)*XST_LD + t] = xv.z;
            XsT[(d0+3)*XST_LD + t] = xv.w;
            float4 wv = wk4[i & 31];
            int dp = (i & 31) * 2;
            float2 k0, k1;
            k0.x = -(xv.x*wv.x); k0.y = -(xv.y*wv.y);
            k1.x = -(xv.z*wv.z); k1.y = -(xv.w*wv.w);
            *(float2*)&KT[(dp    )*168 + t*2] = k0;
            *(float2*)&KT[(dp + 1)*168 + t*2] = k1;
        }
        // zero XsT cols t = 81..89 for all 128 d  (128*9 = 1152)
        for (int i = tid; i < 1152; i += 512) {
            int d = i / 9, t = 81 + (i % 9);
            XsT[d*XST_LD + t] = 0.f;
        }
        const float4 z4 = make_float4(0.f,0.f,0.f,0.f);
        for (int i = tid; i < TT_*LDS_S/4; i += 512)
            ((float4*)S)[i] = z4;                        // zero S (pad cols stay 0)
        // zero KT pad s = 81..83 for all 64 d-pairs
        for (int i = tid; i < 192; i += 512) {
            int dp = i / 3, s = 81 + (i % 3);
            *(float2*)&KT[dp*168 + s*2] = make_float2(0.f, 0.f);
        }
    }

    // W staging map (plain [k-local][n] layout)
    const float* Wg = wqkv_w + ((size_t)h * 2 * DD) * DD;   // 256 rows x 128
    const int wrow = tid >> 1;              // 0..255  (output n)
    const int wkq  = (tid & 1) * 4;         // k-local 0 or 4

    {   // stage chunk 0
        float4 w = *(const float4*)(Wg + wrow*DD + wkq);
        Ws[(wkq+0)*256 + wrow] = w.x;
        Ws[(wkq+1)*256 + wrow] = w.y;
        Ws[(wkq+2)*256 + wrow] = w.z;
        Ws[(wkq+3)*256 + wrow] = w.w;
    }
    __syncthreads();

    // ---------------- P1: QKV GEMM (lanes = (t,t+1) pairs) ----------------
    const int tt = tid >> 5;                // warp id = t-tile (8 t each)
    const int nn = tid & 31;                // 8 n each
    const int t0 = tt * 8;
    const int n0 = nn * 8;
    const bool gemm_act = (tt < 11);

    unsigned long long acc[4][8];           // [t-pair][n]
#pragma unroll
    for (int i = 0; i < 4; i++)
#pragma unroll
        for (int j = 0; j < 8; j++) acc[i][j] = 0ULL;

    int buf = 0;
#pragma unroll 1
    for (int c = 0; c < 16; c++) {
        float4 wnext;
        if (c < 15) wnext = *(const float4*)(Wg + wrow*DD + (c+1)*8 + wkq);
        if (gemm_act) {
            const float* Wb = Ws + buf*2048;
#pragma unroll
            for (int kk = 0; kk < 8; kk++) {
                const int k = c*8 + kk;
                unsigned long long ap[4];
#pragma unroll
                for (int tp = 0; tp < 4; tp++)
                    ap[tp] = *(const unsigned long long*)&XsT[k*XST_LD + t0 + 2*tp];
                float4 w0 = *(const float4*)&Wb[kk*256 + n0];
                float4 w1 = *(const float4*)&Wb[kk*256 + n0 + 4];
                unsigned long long wp[8];
                wp[0] = pack2(w0.x); wp[1] = pack2(w0.y);
                wp[2] = pack2(w0.z); wp[3] = pack2(w0.w);
                wp[4] = pack2(w1.x); wp[5] = pack2(w1.y);
                wp[6] = pack2(w1.z); wp[7] = pack2(w1.w);
#pragma unroll
                for (int tp = 0; tp < 4; tp++)
#pragma unroll
                    for (int j = 0; j < 8; j++)
                        acc[tp][j] = fma2(ap[tp], wp[j], acc[tp][j]);
            }
        }
        if (c < 15) {
            float* Wb2 = Ws + (buf^1)*2048;
            Wb2[(wkq+0)*256 + wrow] = wnext.x;
            Wb2[(wkq+1)*256 + wrow] = wnext.y;
            Wb2[(wkq+2)*256 + wrow] = wnext.z;
            Wb2[(wkq+3)*256 + wrow] = wnext.w;
        }
        __syncthreads();
        buf ^= 1;
    }

    // epilogue: +bias, q -> Qs ; v -> Vs * head_en
    if (gemm_act) {
        const bool isv = (nn >= 16);
        const int d0 = (nn & 15) * 8;
        const float sc = isv ? head_en[h] : 1.0f;
        float* dst = isv ? Vs : Qs;
        float4 bia0 = *(const float4*)(wqkv_b + h*256 + n0);
        float4 bia1 = *(const float4*)(wqkv_b + h*256 + n0 + 4);
#pragma unroll
        for (int tp = 0; tp < 4; tp++) {
            float2 p[8];
#pragma unroll
            for (int j = 0; j < 8; j++) p[j] = unpack2(acc[tp][j]);
            int ta = t0 + 2*tp;
            int tb = ta + 1;
            if (ta < TT_) {
                float4 oa0, oa1;
                oa0.x = (p[0].x + bia0.x)*sc;  oa0.y = (p[1].x + bia0.y)*sc;
                oa0.z = (p[2].x + bia0.z)*sc;  oa0.w = (p[3].x + bia0.w)*sc;
                oa1.x = (p[4].x + bia1.x)*sc;  oa1.y = (p[5].x + bia1.y)*sc;
                oa1.z = (p[6].x + bia1.z)*sc;  oa1.w = (p[7].x + bia1.w)*sc;
                *(float4*)&dst[ta*DD + d0]     = oa0;
                *(float4*)&dst[ta*DD + d0 + 4] = oa1;
            }
            if (tb < TT_) {
                float4 ob0, ob1;
                ob0.x = (p[0].y + bia0.x)*sc;  ob0.y = (p[1].y + bia0.y)*sc;
                ob0.z = (p[2].y + bia0.z)*sc;  ob0.w = (p[3].y + bia0.w)*sc;
                ob1.x = (p[4].y + bia1.x)*sc;  ob1.y = (p[5].y + bia1.y)*sc;
                ob1.z = (p[6].y + bia1.z)*sc;  ob1.w = (p[7].y + bia1.w)*sc;
                *(float4*)&dst[tb*DD + d0]     = ob0;
                *(float4*)&dst[tb*DD + d0 + 4] = ob1;
            }
        }
    }
    __syncthreads();

    // ---------------- P2: scores (+ msk prefetch by idle warps) ----------------
    const float scale = 0.08838834764831843f;   // 1/sqrt(128)
    if (tid >= 448) {
        const float* mg = msk + (size_t)h * TT_ * TT_;
        for (int i = tid - 448; i < TT_*TT_; i += 64) Msk[i] = mg[i];
    } else if (tid < 441) {
        const int t0s = (tid / 21) * 4;
        const int s0 = (tid % 21) * 4;
        int ti[4];
#pragma unroll
        for (int i = 0; i < 4; i++) ti[i] = min(t0s + i, TT_ - 1);

        unsigned long long sacc[4][4];
#pragma unroll
        for (int i = 0; i < 4; i++)
#pragma unroll
            for (int j = 0; j < 4; j++) sacc[i][j] = 0ULL;

#pragma unroll 1
        for (int d = 0; d < DD; d += 4) {
            const int dp = d >> 1;
            // q pairs from Qs rows
            ulonglong2 q[4];
#pragma unroll
            for (int i = 0; i < 4; i++)
                q[i] = *(const ulonglong2*)&Qs[ti[i]*DD + d];
            ulonglong2 ka = *(const ulonglong2*)&KT[(dp  )*168 + s0*2];      // s0, s0+1
            ulonglong2 kb = *(const ulonglong2*)&KT[(dp  )*168 + s0*2 + 4];  // s0+2, s0+3
            ulonglong2 kc = *(const ulonglong2*)&KT[(dp+1)*168 + s0*2];
            ulonglong2 kd = *(const ulonglong2*)&KT[(dp+1)*168 + s0*2 + 4];
#pragma unroll
            for (int i = 0; i < 4; i++) {
                unsigned long long u;
                u = add2(q[i].x, ka.x) & ABS2MASK;  sacc[i][0] = add2(sacc[i][0], u);
                u = add2(q[i].y, kc.x) & ABS2MASK;  sacc[i][0] = add2(sacc[i][0], u);
                u = add2(q[i].x, ka.y) & ABS2MASK;  sacc[i][1] = add2(sacc[i][1], u);
                u = add2(q[i].y, kc.y) & ABS2MASK;  sacc[i][1] = add2(sacc[i][1], u);
                u = add2(q[i].x, kb.x) & ABS2MASK;  sacc[i][2] = add2(sacc[i][2], u);
                u = add2(q[i].y, kd.x) & ABS2MASK;  sacc[i][2] = add2(sacc[i][2], u);
                u = add2(q[i].x, kb.y) & ABS2MASK;  sacc[i][3] = add2(sacc[i][3], u);
                u = add2(q[i].y, kd.y) & ABS2MASK;  sacc[i][3] = add2(sacc[i][3], u);
            }
        }
#pragma unroll
        for (int i = 0; i < 4; i++) {
            if (t0s + i >= TT_) continue;
#pragma unroll
            for (int j = 0; j < 4; j++) {
                if (s0 + j >= TT_) continue;
                float2 f = unpack2(sacc[i][j]);
                S[(s0 + j)*LDS_S + (t0s + i)] = -(f.x + f.y) * scale;
            }
        }
    }
    __syncthreads();

    // ---------------- P3: softmax over s (quad-parallel per t) ----------------
    if (tid < 352) {
        const int t  = tid >> 2;
        const int l4 = tid & 3;
        const bool valid = (t < TT_);
        const int sBeg = l4 * 21;
        const int sEnd = valid ? min(sBeg + 21, TT_) : sBeg;

        float mx = -1e30f;
        for (int s = sBeg; s < sEnd; s++) mx = fmaxf(mx, S[s*LDS_S + t]);
        mx = fmaxf(mx, __shfl_xor_sync(0xFFFFFFFFu, mx, 1));
        mx = fmaxf(mx, __shfl_xor_sync(0xFFFFFFFFu, mx, 2));

        float sum = 0.f;
        for (int s = sBeg; s < sEnd; s++) {
            float e = __expf(S[s*LDS_S + t] - mx);
            sum += e;
            S[s*LDS_S + t] = e;
        }
        sum += __shfl_xor_sync(0xFFFFFFFFu, sum, 1);
        sum += __shfl_xor_sync(0xFFFFFFFFu, sum, 2);
        float inv = 1.f / sum;

        for (int s = sBeg; s < sEnd; s++) {
            float mval = Msk[t*TT_ + s];
            float a = S[s*LDS_S + t] * inv * mval;
            S[s*LDS_S + t] = a;
            if (b == 0)
                ap_out[((size_t)t*TT_ + s)*HH + h] = a - 1.f + mval;
        }
    }
    __syncthreads();

    // ---------------- P4: AV GEMM -> g_bo ----------------
    float* bo = g_bo + (((size_t)b*HH + h)*TT_)*DD;
    if (tid < 336) {                      // 21 t-tiles x 16 d-tiles
        int t0a = (tid >> 4) * 4;
        int d0 = (tid & 15) * 8;
        unsigned long long av[4][4];
#pragma unroll
        for (int i = 0; i < 4; i++)
#pragma unroll
            for (int j = 0; j < 4; j++) av[i][j] = 0ULL;

#pragma unroll 2
        for (int s = 0; s < TT_; s++) {
            float4 a4 = *(const float4*)&S[s*LDS_S + t0a];   // pad cols are 0
            ulonglong2 v0 = *(const ulonglong2*)&Vs[s*DD + d0];
            ulonglong2 v1 = *(const ulonglong2*)&Vs[s*DD + d0 + 4];
            unsigned long long a0 = pack2(a4.x);
            unsigned long long a1 = pack2(a4.y);
            unsigned long long a2v = pack2(a4.z);
            unsigned long long a3 = pack2(a4.w);
            av[0][0] = fma2(a0, v0.x, av[0][0]);
            av[0][1] = fma2(a0, v0.y, av[0][1]);
            av[0][2] = fma2(a0, v1.x, av[0][2]);
            av[0][3] = fma2(a0, v1.y, av[0][3]);
            av[1][0] = fma2(a1, v0.x, av[1][0]);
            av[1][1] = fma2(a1, v0.y, av[1][1]);
            av[1][2] = fma2(a1, v1.x, av[1][2]);
            av[1][3] = fma2(a1, v1.y, av[1][3]);
            av[2][0] = fma2(a2v, v0.x, av[2][0]);
            av[2][1] = fma2(a2v, v0.y, av[2][1]);
            av[2][2] = fma2(a2v, v1.x, av[2][2]);
            av[2][3] = fma2(a2v, v1.y, av[2][3]);
            av[3][0] = fma2(a3, v0.x, av[3][0]);
            av[3][1] = fma2(a3, v0.y, av[3][1]);
            av[3][2] = fma2(a3, v1.x, av[3][2]);
            av[3][3] = fma2(a3, v1.y, av[3][3]);
        }
#pragma unroll
        for (int i = 0; i < 4; i++) {
            int t = t0a + i;
            if (t >= TT_) continue;
            float2 p0 = unpack2(av[i][0]);
            float2 p1 = unpack2(av[i][1]);
            float2 p2 = unpack2(av[i][2]);
            float2 p3 = unpack2(av[i][3]);
            float4 o0 = make_float4(p0.x, p0.y, p1.x, p1.y);
            float4 o1 = make_float4(p2.x, p2.y, p3.x, p3.y);
            *(float4*)&bo[(size_t)t*DD + d0]     = o0;
            *(float4*)&bo[(size_t)t*DD + d0 + 4] = o1;
        }
    }
}

// ---------------------------------------------------------------------------
// Kernel 2: out = x + qgelu(sum_h bo)@Wf^T + bf.  Grid 162:
// (mtile 0..80) x (n-half 0..1). Block = 16 rows x 64 cols, 256 threads.
// Head-reduce + gelu fused into the Gs staging (reads g_bo from L2).
// ---------------------------------------------------------------------------
__device__ __forceinline__ float qgelu4(float s) {
    float u = s + 4.f;
    return u / (1.f + __expf(-1.702f * u)) - 4.f;
}

__global__ void __launch_bounds__(256) fanout_kernel(const float* __restrict__ x,
                                                     const float* __restrict__ Wf,
                                                     const float* __restrict__ bf,
                                                     float* __restrict__ out) {
    extern __shared__ float sm[];
    float* Ws = sm;                 // [128][64]  Ws[k][n]
    float* Gs = sm + 128*64;        // [128][17]  Gs[k*17 + m]
    const int LDG_ = 17;
    const int mtile = blockIdx.x >> 1;
    const int half  = blockIdx.x & 1;
    const int m0 = mtile * 16;
    const int nbase = half * 64;
    const int tid = threadIdx.x;

    // reduce heads + gelu -> Gs (2 slots per thread)
    {
#pragma unroll
        for (int p = 0; p < 2; p++) {
            int i  = p * 256 + tid;     // 0..511
            int ml = i >> 5;
            int kq = i & 31;
            int m = m0 + ml;
            int bb = m / TT_, t = m - bb * TT_;
            const float4* base = (const float4*)g_bo + ((size_t)(bb*HH)*TT_ + t)*32 + kq;
            float s0 = 0.f, s1 = 0.f, s2 = 0.f, s3 = 0.f;
#pragma unroll
            for (int hh = 0; hh < HH; hh++) {
                float4 v = base[(size_t)hh*TT_*32];
                s0 += v.x; s1 += v.y; s2 += v.z; s3 += v.w;
            }
            Gs[(kq*4+0)*LDG_ + ml] = qgelu4(s0);
            Gs[(kq*4+1)*LDG_ + ml] = qgelu4(s1);
            Gs[(kq*4+2)*LDG_ + ml] = qgelu4(s2);
            Gs[(kq*4+3)*LDG_ + ml] = qgelu4(s3);
        }
    }
    // stage Wf half -> Ws[k][n]
    {
        int n  = tid & 63;
        int k4 = tid >> 6;              // 0..3
        const float* wr = Wf + (size_t)(nbase + n) * DD;
#pragma unroll
        for (int p = 0; p < 8; p++) {
            int kq = p * 4 + k4;        // 0..31
            float4 w = *(const float4*)(wr + kq * 4);
            Ws[(kq*4+0)*64 + n] = w.x;
            Ws[(kq*4+1)*64 + n] = w.y;
            Ws[(kq*4+2)*64 + n] = w.z;
            Ws[(kq*4+3)*64 + n] = w.w;
        }
    }
    __syncthreads();

    const int m_ = tid >> 4;            // 0..15
    const int n0 = (tid & 15) * 4;      // 0..60
    float a0 = 0.f, a1 = 0.f, a2 = 0.f, a3 = 0.f;
#pragma unroll 8
    for (int k = 0; k < 128; k++) {
        float g = Gs[k*LDG_ + m_];
        float4 w = *(const float4*)&Ws[k*64 + n0];
        a0 += g * w.x; a1 += g * w.y; a2 += g * w.z; a3 += g * w.w;
    }
    int m = m0 + m_;
    int ng = nbase + n0;
    float4 xv = *(const float4*)&x[(size_t)m*DD + ng];
    float4 bv = *(const float4*)&bf[ng];
    float4 o;
    o.x = xv.x + a0 + bv.x;
    o.y = xv.y + a1 + bv.y;
    o.z = xv.z + a2 + bv.z;
    o.w = xv.w + a3 + bv.w;
    *(float4*)&out[(size_t)m*DD + ng] = o;
}

// ---------------------------------------------------------------------------
extern "C" void kernel_launch(void* const* d_in, const int* in_sizes, int n_in,
                              void* d_out, int out_size) {
    const float* x        = (const float*)d_in[0];
    const float* msk      = (const float*)d_in[1];
    const float* wqkv_w   = (const float*)d_in[2];
    const float* wqkv_b   = (const float*)d_in[3];
    const float* wk_w     = (const float*)d_in[4];
    const float* fanout_w = (const float*)d_in[5];
    const float* fanout_b = (const float*)d_in[6];
    const float* head_en  = (const float*)d_in[7];

    float* out = (float*)d_out;
    float* ap_out = out + (size_t)BT * DD;   // 165888 onward

    const int smemA = SMEM_FLOATS * 4;                   // 215632
    const int smem3 = (128*64 + 128*17) * 4 + 16;        // ~41.5KB

    cudaFuncSetAttribute(attn_fused,    cudaFuncAttributeMaxDynamicSharedMemorySize, smemA);
    cudaFuncSetAttribute(fanout_kernel, cudaFuncAttributeMaxDynamicSharedMemorySize, smem3);

    attn_fused<<<BB * HH, 512, smemA>>>(x, wqkv_w, wqkv_b, wk_w, msk, head_en, ap_out);

    fanout_kernel<<<162, 256, smem3>>>(x, fanout_w, fanout_b, out);
}